// round 1
// baseline (speedup 1.0000x reference)
#include <cuda_runtime.h>

#define N_FFT   16384
#define THREADS 512
#define PI_F    3.14159265358979323846f

// W_32^j = e^{-2*pi*i*j/32} = (cos(pi*j/16), -sin(pi*j/16)), j = 0..15
__constant__ float TW_COS[16] = {
    1.000000000000000f,  0.980785280403230f,  0.923879532511287f,  0.831469612302545f,
    0.707106781186548f,  0.555570233019602f,  0.382683432365090f,  0.195090322016128f,
    0.000000000000000f, -0.195090322016128f, -0.382683432365090f, -0.555570233019602f,
   -0.707106781186548f, -0.831469612302545f, -0.923879532511287f, -0.980785280403230f
};
__constant__ float TW_SIN[16] = {
    0.000000000000000f,  0.195090322016128f,  0.382683432365090f,  0.555570233019602f,
    0.707106781186548f,  0.831469612302545f,  0.923879532511287f,  0.980785280403230f,
    1.000000000000000f,  0.980785280403230f,  0.923879532511287f,  0.831469612302545f,
    0.707106781186548f,  0.555570233019602f,  0.382683432365090f,  0.195090322016128f
};

struct cplx { float x, y; };

__device__ __forceinline__ int swz(int p) {
    return p ^ (((p >> 5) ^ (p >> 10)) & 31);
}

// In-place DIF radix-2 FFT of size R (power of 2, R <= 32).
// Natural-order input, bit-reversed-order output: r[i] = X[bitrev(i)].
template<int R>
__device__ __forceinline__ void fft_dif(cplx* r) {
    #pragma unroll
    for (int half = R / 2; half >= 1; half >>= 1) {
        #pragma unroll
        for (int base = 0; base < R; base += 2 * half) {
            #pragma unroll
            for (int j = 0; j < half; j++) {
                cplx a = r[base + j];
                cplx b = r[base + half + j];
                r[base + j].x = a.x + b.x;
                r[base + j].y = a.y + b.y;
                float dx = a.x - b.x;
                float dy = a.y - b.y;
                const int tw = j * (16 / half);   // index into W_32 table
                if (tw == 0) {
                    r[base + half + j].x = dx;
                    r[base + half + j].y = dy;
                } else if (tw == 8) {
                    // W = (0, -1): d * W = (dy, -dx)
                    r[base + half + j].x = dy;
                    r[base + half + j].y = -dx;
                } else {
                    float wc = TW_COS[tw];
                    float ws = TW_SIN[tw];
                    // d * (wc, -ws)
                    r[base + half + j].x = dx * wc + dy * ws;
                    r[base + half + j].y = dy * wc - dx * ws;
                }
            }
        }
    }
}

__global__ void __launch_bounds__(THREADS, 1)
idxct_kernel(const float* __restrict__ x,
             const float2* __restrict__ expk,
             float* __restrict__ y)
{
    extern __shared__ float smem[];
    float* sre = smem;
    float* sim = smem + N_FFT;

    const int row = blockIdx.x;
    const int t   = threadIdx.x;
    const float* xr = x + (size_t)row * N_FFT;

    // ---------------- Pass 1: radix-32 over n1 (stride 512), n2 = t ----------------
    {
        cplx r[32];
        #pragma unroll
        for (int n1 = 0; n1 < 32; n1++) {
            int n = n1 * 512 + t;
            float  xv = xr[n];
            float2 e  = expk[n];         // (cos, -sin) of pi*n/(2N)
            r[n1].x = xv * e.x;          // t_n = x_n * e^{-j*pi*n/(2N)}
            r[n1].y = xv * e.y;
        }
        fft_dif<32>(r);
        #pragma unroll
        for (int i = 0; i < 32; i++) {
            int k1 = __brev((unsigned)i) >> 27;
            // twiddle W_16384^{t*k1}
            float s, c;
            __sincosf(-PI_F * (float)(t * k1) * (1.0f / 8192.0f), &s, &c);
            float vx = r[i].x * c - r[i].y * s;
            float vy = r[i].x * s + r[i].y * c;
            int p = swz(k1 * 512 + t);
            sre[p] = vx;
            sim[p] = vy;
        }
    }
    __syncthreads();

    // ---------------- Pass 2: radix-32 over a (stride 16 within each 512-block) ----
    {
        const int k1 = t & 31;       // lane == k1 -> conflict-free
        const int b  = t >> 5;       // [0,16)
        cplx r[32];
        #pragma unroll
        for (int a = 0; a < 32; a++) {
            int p = swz(k1 * 512 + a * 16 + b);
            r[a].x = sre[p];
            r[a].y = sim[p];
        }
        fft_dif<32>(r);
        #pragma unroll
        for (int i = 0; i < 32; i++) {
            int c = __brev((unsigned)i) >> 27;
            // twiddle W_512^{b*c}
            float s, cc;
            __sincosf(-PI_F * (float)(b * c) * (1.0f / 256.0f), &s, &cc);
            float vx = r[i].x * cc - r[i].y * s;
            float vy = r[i].x * s  + r[i].y * cc;
            int p = swz(k1 * 512 + c * 16 + b);
            sre[p] = vx;
            sim[p] = vy;
        }
    }
    __syncthreads();

    // ---------------- Pass 3: radix-16 over b (contiguous 16) — real output only ---
    {
        const int k1 = t & 31;
        const int c0 = t >> 5;       // [0,16); this thread does c0 and c0+16
        #pragma unroll
        for (int h = 0; h < 2; h++) {
            const int c = c0 + 16 * h;
            cplx r[16];
            #pragma unroll
            for (int b = 0; b < 16; b++) {
                int p = swz(k1 * 512 + c * 16 + b);
                r[b].x = sre[p];
                r[b].y = sim[p];
            }
            fft_dif<16>(r);
            #pragma unroll
            for (int i = 0; i < 16; i++) {
                int d = __brev((unsigned)i) >> 28;
                int p = swz(k1 * 512 + c * 16 + d);
                sre[p] = r[i].x;     // only Re(T) is needed downstream
            }
        }
    }
    __syncthreads();

    // ---------------- Gather: y_{2m} = Re T_m ; y_{2m+1} = Re T_{N-1-m} ------------
    // T[k1 + 32*c + 1024*d] lives at smem position 512*k1 + 16*c + d (swizzled).
    {
        float* yr = y + (size_t)row * N_FFT;
        #pragma unroll
        for (int j = 0; j < 32; j++) {
            int o = t + 512 * j;
            int m = (o & 1) ? (N_FFT - 1 - (o >> 1)) : (o >> 1);
            int p = swz((m & 31) * 512 + ((m >> 5) & 31) * 16 + (m >> 10));
            yr[o] = sre[p];
        }
    }
}

extern "C" void kernel_launch(void* const* d_in, const int* in_sizes, int n_in,
                              void* d_out, int out_size)
{
    const float*  x    = (const float*)d_in[0];
    const float2* expk = (const float2*)d_in[1];
    float*        y    = (float*)d_out;

    const int rows = in_sizes[0] / N_FFT;
    const int smem_bytes = 2 * N_FFT * (int)sizeof(float);   // 128 KB

    cudaFuncSetAttribute(idxct_kernel,
                         cudaFuncAttributeMaxDynamicSharedMemorySize, smem_bytes);

    idxct_kernel<<<rows, THREADS, smem_bytes>>>(x, expk, y);
}

// round 5
// speedup vs baseline: 1.8280x; 1.8280x over previous
#include <cuda_runtime.h>

#define NFFT 16384
#define HN   8192      // N/2  (size of the complex IFFT)
#define QN   4096      // N/4  (each sub-FFT)
#define THREADS 256
#define PI_F 3.14159265358979323846f
#define SQRT_HALF 0.70710678118654752440f

// Inverse-FFT radix-16 twiddles: W_16^j = e^{+j*2*pi*j/16}, j=0..7
__constant__ float C16[8] = {
    1.0f, 0.92387953251128675613f, 0.70710678118654752440f, 0.38268343236508977173f,
    0.0f,-0.38268343236508977173f,-0.70710678118654752440f,-0.92387953251128675613f };
__constant__ float S16[8] = {
    0.0f, 0.38268343236508977173f, 0.70710678118654752440f, 0.92387953251128675613f,
    1.0f, 0.92387953251128675613f, 0.70710678118654752440f, 0.38268343236508977173f };

struct cplx { float x, y; };

// In-place DIF radix-16 inverse FFT (e^{+j}). Natural in, bit-reversed out:
// r[i] holds output digit rev4(i).
__device__ __forceinline__ void fft16_inv(cplx* r) {
    #pragma unroll
    for (int half = 8; half >= 1; half >>= 1) {
        #pragma unroll
        for (int base = 0; base < 16; base += 2 * half) {
            #pragma unroll
            for (int j = 0; j < half; j++) {
                cplx a = r[base + j];
                cplx b = r[base + half + j];
                r[base + j].x = a.x + b.x;
                r[base + j].y = a.y + b.y;
                float dx = a.x - b.x, dy = a.y - b.y;
                const int tw = j * (8 / half);
                if (tw == 0)      { r[base+half+j].x = dx;  r[base+half+j].y = dy; }
                else if (tw == 4) { r[base+half+j].x = -dy; r[base+half+j].y = dx; }  // *(+j)
                else {
                    float c = C16[tw], s = S16[tw];
                    r[base+half+j].x = dx * c - dy * s;
                    r[base+half+j].y = dx * s + dy * c;
                }
            }
        }
    }
}

// Bank swizzle for the 4096-point sub-FFT region (digits k1*256 + a*16 + b).
__device__ __forceinline__ int swz12(int p) {
    return p ^ (((p >> 8) << 1) & 30) ^ ((p >> 4) & 1);
}
// Bank swizzle for the raw-x staging region (16384 floats).
__device__ __forceinline__ int sxz(int i) {
    return i ^ (((i >> 5) & 7) << 2);
}

__global__ void __launch_bounds__(THREADS, 2)
idxct_kernel(const float* __restrict__ x, float* __restrict__ y)
{
    extern __shared__ float smem[];
    float* sre = smem;          // after phase 1: Re z, [0,8192)
    float* sim = smem + HN;     // Im z

    const int row  = blockIdx.x;
    const int t    = threadIdx.x;
    const int half = t >> 7;         // 0 = A (even spectrum), 1 = B (odd)
    const int th   = t & 127;
    const int hoff = half << 12;     // 0 or 4096

    // ---- Phase 0: coalesced stage of x into smem (swizzled) --------------
    {
        const float4* x4 = (const float4*)(x + (size_t)row * NFFT);
        #pragma unroll
        for (int j = 0; j < 16; j++) {
            int idx = t + THREADS * j;
            float4 v = x4[idx];
            *(float4*)(smem + sxz(idx << 2)) = v;
        }
    }
    __syncthreads();

    cplx r[2][16];

    // ---- Phase 1a: build spectrum q_m (m = 2u for A, 2u+1 for B) ---------
    // s_m = conj(expk_m) * (x_m - j x_{N-m});   s_0 = 2 x_0
    // q_m = 0.5 * [ (s_m + s_{m+H}) + j*tau_m*(s_m - s_{m+H}) ],  tau = e^{j*pi*m/H}
    #pragma unroll
    for (int j = 0; j < 2; j++) {
        const int tp = th + 128 * j;            // t' in [0,256)
        #pragma unroll
        for (int n1 = 0; n1 < 16; n1++) {
            int u = n1 * 256 + tp;
            int m = 2 * u + half;               // [0, 8192)
            float sb, cb;
            __sincosf((float)m * (PI_F / 32768.0f), &sb, &cb);   // e1 = e^{+j*pi*m/(2N)}
            float e2x = (cb - sb) * SQRT_HALF;                   // e2 = e1 * e^{j*pi/4}
            float e2y = (cb + sb) * SQRT_HALF;
            float t2x = cb*cb - sb*sb, t2y = 2.0f*cb*sb;         // tau = e1^4
            float tx  = t2x*t2x - t2y*t2y, ty = 2.0f*t2x*t2y;

            float xm  = smem[sxz(m)];
            float xmH = smem[sxz(m + HN)];
            float xHm = smem[sxz(HN - m)];
            float s1x, s1y;
            if (m == 0) {
                s1x = 2.0f * xm; s1y = 0.0f;
            } else {
                float xNm = smem[sxz(NFFT - m)];
                s1x = xm * cb + xNm * sb;
                s1y = xm * sb - xNm * cb;
            }
            float s2x = xmH * e2x + xHm * e2y;
            float s2y = xmH * e2y - xHm * e2x;
            float ux = s1x + s2x, uy = s1y + s2y;
            float vx = s1x - s2x, vy = s1y - s2y;
            r[j][n1].x = 0.5f * (ux - (tx * vy + ty * vx));
            r[j][n1].y = 0.5f * (uy + (tx * vx - ty * vy));
        }
    }
    __syncthreads();   // all x reads done before overwriting smem

    // ---- Pass 1: radix-16 over n1, twiddle W_4096^{+t'*k1} ---------------
    #pragma unroll
    for (int j = 0; j < 2; j++) {
        fft16_inv(r[j]);
        const int tp = th + 128 * j;
        #pragma unroll
        for (int i = 0; i < 16; i++) {
            int k1 = __brev((unsigned)i) >> 28;
            float s, c;
            __sincosf((float)(tp * k1) * (2.0f * PI_F / 4096.0f), &s, &c);
            float vx = r[j][i].x * c - r[j][i].y * s;
            float vy = r[j][i].x * s + r[j][i].y * c;
            int p = hoff + swz12(k1 * 256 + tp);
            sre[p] = vx; sim[p] = vy;
        }
    }
    __syncthreads();

    // ---- Pass 2: radix-16 over middle digit, twiddle W_256^{+b*k2} -------
    // j=0 touches b in [0,8), j=1 touches b in [8,16): disjoint, no barrier.
    #pragma unroll
    for (int j = 0; j < 2; j++) {
        const int k1 = th & 15;
        const int b  = (th >> 4) + 8 * j;
        #pragma unroll
        for (int a = 0; a < 16; a++) {
            int p = hoff + swz12(k1 * 256 + a * 16 + b);
            r[j][a].x = sre[p]; r[j][a].y = sim[p];
        }
        fft16_inv(r[j]);
        #pragma unroll
        for (int i = 0; i < 16; i++) {
            int k2 = __brev((unsigned)i) >> 28;
            float s, c;
            __sincosf((float)(b * k2) * (2.0f * PI_F / 256.0f), &s, &c);
            float vx = r[j][i].x * c - r[j][i].y * s;
            float vy = r[j][i].x * s + r[j][i].y * c;
            int p = hoff + swz12(k1 * 256 + k2 * 16 + b);
            sre[p] = vx; sim[p] = vy;
        }
    }
    __syncthreads();

    // ---- Pass 3: radix-16 over low digit, no twiddle ---------------------
    #pragma unroll
    for (int j = 0; j < 2; j++) {
        const int k1 = th & 15;
        const int c  = (th >> 4) + 8 * j;
        #pragma unroll
        for (int bq = 0; bq < 16; bq++) {
            int p = hoff + swz12(k1 * 256 + c * 16 + bq);
            r[j][bq].x = sre[p]; r[j][bq].y = sim[p];
        }
        fft16_inv(r[j]);
        #pragma unroll
        for (int i = 0; i < 16; i++) {
            int k3 = __brev((unsigned)i) >> 28;
            int p = hoff + swz12(k1 * 256 + c * 16 + k3);
            sre[p] = r[j][i].x; sim[p] = r[j][i].y;
        }
    }
    __syncthreads();

    // ---- Gather: combine halves + de-permute, contiguous float4 stores ---
    // z_q       = A_q       + w^q * B_q,         w = e^{+j*2*pi/8192}
    // z_{8191-q}= A_{4095-q} - w^{4095-q} * B_{4095-q},  w^{4095-q} = -conj(w^{q+1})
    // y[4q]=Re z_q, y[4q+1]=Im z_{8191-q}, y[4q+2]=Im z_q, y[4q+3]=Re z_{8191-q}
    {
        float4* y4 = (float4*)(y + (size_t)row * NFFT);
        const float c1 = 0.99999970586288222663f;      // cos(2*pi/8192)
        const float s1 = 7.66990318742704526939e-4f;   // sin(2*pi/8192)
        #pragma unroll
        for (int j = 0; j < 16; j++) {
            int q  = t + THREADS * j;                  // [0, 4096)
            int d0 = q & 15, d1 = (q >> 4) & 15, d2 = q >> 8;
            int pA = swz12(d0 * 256 + d1 * 16 + d2);
            int pM = swz12((15 - d0) * 256 + (15 - d1) * 16 + (15 - d2));
            float Ax = sre[pA],      Ay = sim[pA];
            float Bx = sre[pA + QN], By = sim[pA + QN];
            float Mx = sre[pM],      My = sim[pM];
            float Nx = sre[pM + QN], Ny = sim[pM + QN];
            float ws, wc;
            __sincosf((float)q * (2.0f * PI_F / 8192.0f), &ws, &wc);
            float ox = wc * c1 - ws * s1;              // w^{q+1}
            float oy = wc * s1 + ws * c1;
            float z1x = Ax + (wc * Bx - ws * By);
            float z1y = Ay + (wc * By + ws * Bx);
            float z2x = Mx + (ox * Nx + oy * Ny);
            float z2y = My + (ox * Ny - oy * Nx);
            y4[q] = make_float4(z1x, z2y, z1y, z2x);
        }
    }
}

extern "C" void kernel_launch(void* const* d_in, const int* in_sizes, int n_in,
                              void* d_out, int out_size)
{
    const float* x = (const float*)d_in[0];
    float*       y = (float*)d_out;

    const int rows = in_sizes[0] / NFFT;
    const int smem_bytes = NFFT * (int)sizeof(float);   // 64 KB

    cudaFuncSetAttribute(idxct_kernel,
                         cudaFuncAttributeMaxDynamicSharedMemorySize, smem_bytes);

    idxct_kernel<<<rows, THREADS, smem_bytes>>>(x, y);
}

// round 6
// speedup vs baseline: 1.8818x; 1.0294x over previous
#include <cuda_runtime.h>

#define NFFT 16384
#define HN   8192      // N/2  (size of the complex IFFT)
#define QN   4096      // N/4  (each sub-FFT)
#define THREADS 256
#define PI_F 3.14159265358979323846f
#define SQRT_HALF 0.70710678118654752440f

// Inverse-FFT radix-16 twiddles: W_16^j = e^{+j*2*pi*j/16}, j=0..7
__constant__ float C16[8] = {
    1.0f, 0.92387953251128675613f, 0.70710678118654752440f, 0.38268343236508977173f,
    0.0f,-0.38268343236508977173f,-0.70710678118654752440f,-0.92387953251128675613f };
__constant__ float S16[8] = {
    0.0f, 0.38268343236508977173f, 0.70710678118654752440f, 0.92387953251128675613f,
    1.0f, 0.92387953251128675613f, 0.70710678118654752440f, 0.38268343236508977173f };

struct cplx { float x, y; };

// In-place DIF radix-16 inverse FFT (e^{+j}). Natural in, bit-reversed out:
// r[i] holds output digit rev4(i).
__device__ __forceinline__ void fft16_inv(cplx* r) {
    #pragma unroll
    for (int half = 8; half >= 1; half >>= 1) {
        #pragma unroll
        for (int base = 0; base < 16; base += 2 * half) {
            #pragma unroll
            for (int j = 0; j < half; j++) {
                cplx a = r[base + j];
                cplx b = r[base + half + j];
                r[base + j].x = a.x + b.x;
                r[base + j].y = a.y + b.y;
                float dx = a.x - b.x, dy = a.y - b.y;
                const int tw = j * (8 / half);
                if (tw == 0)      { r[base+half+j].x = dx;  r[base+half+j].y = dy; }
                else if (tw == 4) { r[base+half+j].x = -dy; r[base+half+j].y = dx; }  // *(+j)
                else {
                    float c = C16[tw], s = S16[tw];
                    r[base+half+j].x = dx * c - dy * s;
                    r[base+half+j].y = dx * s + dy * c;
                }
            }
        }
    }
}

// Bank swizzle for the 4096-point sub-FFT region (digits k1*256 + a*16 + b).
__device__ __forceinline__ int swz12(int p) {
    return p ^ (((p >> 8) << 1) & 30) ^ ((p >> 4) & 1);
}
// Bank swizzle for the raw-x staging region (16384 floats).
__device__ __forceinline__ int sxz(int i) {
    return i ^ (((i >> 5) & 7) << 2);
}

__global__ void __launch_bounds__(THREADS, 2)
idxct_kernel(const float* __restrict__ x, float* __restrict__ y)
{
    extern __shared__ float smem[];
    float* sre = smem;          // after phase 1: Re z, [0,8192)
    float* sim = smem + HN;     // Im z

    const int row  = blockIdx.x;
    const int t    = threadIdx.x;
    const int half = t >> 7;         // 0 = A (even spectrum), 1 = B (odd)
    const int th   = t & 127;
    const int hoff = half << 12;     // 0 or 4096

    // digit-reverse (base-16) of 0..15, used with literal indices only
    const int REV4[16] = {0,8,4,12,2,10,6,14,1,9,5,13,3,11,7,15};

    // ---- Phase 0: coalesced stage of x into smem (swizzled) --------------
    {
        const float4* x4 = (const float4*)(x + (size_t)row * NFFT);
        #pragma unroll
        for (int j = 0; j < 16; j++) {
            int idx = t + THREADS * j;
            float4 v = x4[idx];
            *(float4*)(smem + sxz(idx << 2)) = v;
        }
    }
    __syncthreads();

    cplx r[2][16];

    // ---- Phase 1a: build spectrum q_m (m = 2u for A, 2u+1 for B) ---------
    // s_m = conj(expk_m) * (x_m - j x_{N-m});   s_0 = 2 x_0
    // q_m = 0.5 * [ (s_m + s_{m+H}) + j*tau_m*(s_m - s_{m+H}) ],  tau = e1^4
    // e1 = e^{+j*pi*m/32768}; m steps by 512 across n1 -> rotate by pi/64.
    {
        const float cD = 0.99879545620517239271f;   // cos(pi/64)
        const float sD = 0.04906767432741801426f;   // sin(pi/64)
        #pragma unroll
        for (int j = 0; j < 2; j++) {
            const int tp = th + 128 * j;            // t' in [0,256)
            const int m0 = 2 * tp + half;
            float cb, sb;
            __sincosf((float)m0 * (PI_F / 32768.0f), &sb, &cb);
            #pragma unroll
            for (int n1 = 0; n1 < 16; n1++) {
                int m = 512 * n1 + m0;              // [0, 8192)
                float e2x = (cb - sb) * SQRT_HALF;  // e2 = e1 * e^{j*pi/4}
                float e2y = (cb + sb) * SQRT_HALF;
                float t2x = 2.0f * e2x * e2y;       // = cb^2 - sb^2
                float t2y = 2.0f * cb * sb;
                float tx  = t2x*t2x - t2y*t2y, ty = 2.0f*t2x*t2y;   // tau = e1^4

                float xm  = smem[sxz(m)];
                float xmH = smem[sxz(m + HN)];
                float xHm = smem[sxz(HN - m)];
                float s1x, s1y;
                if (m == 0) {
                    s1x = 2.0f * xm; s1y = 0.0f;
                } else {
                    float xNm = smem[sxz(NFFT - m)];
                    s1x = xm * cb + xNm * sb;
                    s1y = xm * sb - xNm * cb;
                }
                float s2x = xmH * e2x + xHm * e2y;
                float s2y = xmH * e2y - xHm * e2x;
                float ux = s1x + s2x, uy = s1y + s2y;
                float vx = s1x - s2x, vy = s1y - s2y;
                r[j][n1].x = 0.5f * (ux - (tx * vy + ty * vx));
                r[j][n1].y = 0.5f * (uy + (tx * vx - ty * vy));

                float ncb = cb * cD - sb * sD;      // e1 *= e^{j*pi/64}
                sb = sb * cD + cb * sD;
                cb = ncb;
            }
        }
    }
    __syncthreads();   // all x reads done before overwriting smem

    // ---- Pass 1: radix-16 over n1, twiddle W_4096^{+t'*k1} ---------------
    #pragma unroll
    for (int j = 0; j < 2; j++) {
        fft16_inv(r[j]);
        const int tp = th + 128 * j;
        float w1s, w1c;
        __sincosf((float)tp * (2.0f * PI_F / 4096.0f), &w1s, &w1c);
        float wc = 1.0f, ws = 0.0f;                 // w^0
        #pragma unroll
        for (int k1 = 0; k1 < 16; k1++) {
            const int i = REV4[k1];                 // literal under unroll
            float vx = r[j][i].x * wc - r[j][i].y * ws;
            float vy = r[j][i].x * ws + r[j][i].y * wc;
            int p = hoff + swz12(k1 * 256 + tp);
            sre[p] = vx; sim[p] = vy;
            float nwc = wc * w1c - ws * w1s;        // w *= w1
            ws = ws * w1c + wc * w1s;
            wc = nwc;
        }
    }
    __syncthreads();

    // ---- Pass 2: radix-16 over middle digit, twiddle W_256^{+b*k2} -------
    // j=0 touches b in [0,8), j=1 touches b in [8,16): disjoint, no barrier.
    #pragma unroll
    for (int j = 0; j < 2; j++) {
        const int k1 = th & 15;
        const int b  = (th >> 4) + 8 * j;
        #pragma unroll
        for (int a = 0; a < 16; a++) {
            int p = hoff + swz12(k1 * 256 + a * 16 + b);
            r[j][a].x = sre[p]; r[j][a].y = sim[p];
        }
        fft16_inv(r[j]);
        float w1s, w1c;
        __sincosf((float)b * (PI_F / 128.0f), &w1s, &w1c);
        float wc = 1.0f, ws = 0.0f;
        #pragma unroll
        for (int k2 = 0; k2 < 16; k2++) {
            const int i = REV4[k2];
            float vx = r[j][i].x * wc - r[j][i].y * ws;
            float vy = r[j][i].x * ws + r[j][i].y * wc;
            int p = hoff + swz12(k1 * 256 + k2 * 16 + b);
            sre[p] = vx; sim[p] = vy;
            float nwc = wc * w1c - ws * w1s;
            ws = ws * w1c + wc * w1s;
            wc = nwc;
        }
    }
    __syncthreads();

    // ---- Pass 3: radix-16 over low digit, no twiddle ---------------------
    #pragma unroll
    for (int j = 0; j < 2; j++) {
        const int k1 = th & 15;
        const int c  = (th >> 4) + 8 * j;
        #pragma unroll
        for (int bq = 0; bq < 16; bq++) {
            int p = hoff + swz12(k1 * 256 + c * 16 + bq);
            r[j][bq].x = sre[p]; r[j][bq].y = sim[p];
        }
        fft16_inv(r[j]);
        #pragma unroll
        for (int i = 0; i < 16; i++) {
            int k3 = REV4[i];
            int p = hoff + swz12(k1 * 256 + c * 16 + k3);
            sre[p] = r[j][i].x; sim[p] = r[j][i].y;
        }
    }
    __syncthreads();

    // ---- Gather: combine halves + de-permute, contiguous float4 stores ---
    // z_q       = A_q       + w^q * B_q,         w = e^{+j*2*pi/8192}
    // z_{8191-q}= A_{4095-q} - w^{4095-q} * B_{4095-q},  w^{4095-q} = -conj(w^{q+1})
    // y[4q]=Re z_q, y[4q+1]=Im z_{8191-q}, y[4q+2]=Im z_q, y[4q+3]=Re z_{8191-q}
    {
        float4* y4 = (float4*)(y + (size_t)row * NFFT);
        const float c1 = 0.99999970586288222663f;      // cos(2*pi/8192)
        const float s1 = 7.66990318742704526939e-4f;   // sin(2*pi/8192)
        const float cS = 0.98078528040323044913f;      // cos(pi/16)   (step: q += 256)
        const float sS = 0.19509032201612826785f;      // sin(pi/16)
        float wc, ws;
        __sincosf((float)t * (2.0f * PI_F / 8192.0f), &ws, &wc);
        #pragma unroll
        for (int j = 0; j < 16; j++) {
            int q  = t + THREADS * j;                  // [0, 4096)
            int d0 = q & 15, d1 = (q >> 4) & 15, d2 = q >> 8;
            int pA = swz12(d0 * 256 + d1 * 16 + d2);
            int pM = swz12((15 - d0) * 256 + (15 - d1) * 16 + (15 - d2));
            float Ax = sre[pA],      Ay = sim[pA];
            float Bx = sre[pA + QN], By = sim[pA + QN];
            float Mx = sre[pM],      My = sim[pM];
            float Nx = sre[pM + QN], Ny = sim[pM + QN];
            float ox = wc * c1 - ws * s1;              // w^{q+1}
            float oy = wc * s1 + ws * c1;
            float z1x = Ax + (wc * Bx - ws * By);
            float z1y = Ay + (wc * By + ws * Bx);
            float z2x = Mx + (ox * Nx + oy * Ny);
            float z2y = My + (ox * Ny - oy * Nx);
            y4[q] = make_float4(z1x, z2y, z1y, z2x);
            float nwc = wc * cS - ws * sS;             // w *= e^{j*pi/16}
            ws = ws * cS + wc * sS;
            wc = nwc;
        }
    }
}

extern "C" void kernel_launch(void* const* d_in, const int* in_sizes, int n_in,
                              void* d_out, int out_size)
{
    const float* x = (const float*)d_in[0];
    float*       y = (float*)d_out;

    const int rows = in_sizes[0] / NFFT;
    const int smem_bytes = NFFT * (int)sizeof(float);   // 64 KB

    cudaFuncSetAttribute(idxct_kernel,
                         cudaFuncAttributeMaxDynamicSharedMemorySize, smem_bytes);

    idxct_kernel<<<rows, THREADS, smem_bytes>>>(x, y);
}

// round 7
// speedup vs baseline: 1.9674x; 1.0455x over previous
#include <cuda_runtime.h>

#define NFFT 16384
#define HN   8192      // N/2  (size of the complex IFFT)
#define QN   4096      // N/4  (each sub-FFT)
#define THREADS 256
#define PI_F 3.14159265358979323846f
#define SQRT_HALF 0.70710678118654752440f

// Inverse-FFT radix-16 twiddles: W_16^j = e^{+j*2*pi*j/16}, j=0..7
__constant__ float C16[8] = {
    1.0f, 0.92387953251128675613f, 0.70710678118654752440f, 0.38268343236508977173f,
    0.0f,-0.38268343236508977173f,-0.70710678118654752440f,-0.92387953251128675613f };
__constant__ float S16[8] = {
    0.0f, 0.38268343236508977173f, 0.70710678118654752440f, 0.92387953251128675613f,
    1.0f, 0.92387953251128675613f, 0.70710678118654752440f, 0.38268343236508977173f };

struct cplx { float x, y; };

// Packed complex add: one ADD.f32x2 issue (vs 2 scalar FADD).
__device__ __forceinline__ cplx padd(cplx a, cplx b) {
    cplx r;
    asm("{\n\t"
        ".reg .b64 ra, rb, rr;\n\t"
        "mov.b64 ra, {%2, %3};\n\t"
        "mov.b64 rb, {%4, %5};\n\t"
        "add.rn.f32x2 rr, ra, rb;\n\t"
        "mov.b64 {%0, %1}, rr;\n\t"
        "}"
        : "=f"(r.x), "=f"(r.y)
        : "f"(a.x), "f"(a.y), "f"(b.x), "f"(b.y));
    return r;
}

// Packed complex sub via FMA2 with (-1,-1): a + (-1)*b, bit-exact vs FSUB.
__device__ __forceinline__ cplx psub(cplx a, cplx b, unsigned long long neg1) {
    cplx r;
    asm("{\n\t"
        ".reg .b64 ra, rb, rr;\n\t"
        "mov.b64 ra, {%2, %3};\n\t"
        "mov.b64 rb, {%4, %5};\n\t"
        "fma.rn.f32x2 rr, rb, %6, ra;\n\t"
        "mov.b64 {%0, %1}, rr;\n\t"
        "}"
        : "=f"(r.x), "=f"(r.y)
        : "f"(a.x), "f"(a.y), "f"(b.x), "f"(b.y), "l"(neg1));
    return r;
}

// In-place DIF radix-16 inverse FFT (e^{+j}). Natural in, digit-reversed out.
__device__ __forceinline__ void fft16_inv(cplx* r, unsigned long long neg1) {
    #pragma unroll
    for (int half = 8; half >= 1; half >>= 1) {
        #pragma unroll
        for (int base = 0; base < 16; base += 2 * half) {
            #pragma unroll
            for (int j = 0; j < half; j++) {
                cplx a = r[base + j];
                cplx b = r[base + half + j];
                r[base + j] = padd(a, b);
                cplx d = psub(a, b, neg1);
                const int tw = j * (8 / half);
                if (tw == 0)      { r[base+half+j] = d; }
                else if (tw == 4) { r[base+half+j].x = -d.y; r[base+half+j].y = d.x; }  // *(+j)
                else {
                    float c = C16[tw], s = S16[tw];
                    r[base+half+j].x = d.x * c - d.y * s;
                    r[base+half+j].y = d.x * s + d.y * c;
                }
            }
        }
    }
}

// Swizzle for the complex (float2) region: XOR low digit with high digit.
// All pass/gather patterns are conflict-free per 16-lane phase under this map,
// and a*16 / k2*16 offsets never carry into the XORed low-4 bits -> LDS imm offsets.
__device__ __forceinline__ int swc(int p) { return p ^ ((p >> 8) & 15); }
// Swizzle for the raw-x float staging region.
__device__ __forceinline__ int sxz(int i) { return i ^ (((i >> 5) & 7) << 2); }

__global__ void __launch_bounds__(THREADS, 2)
idxct_kernel(const float* __restrict__ x, float* __restrict__ y)
{
    extern __shared__ float smem[];
    float2* cz = (float2*)smem;      // 8192 complex after pass 1 (aliases x staging)

    const int row  = blockIdx.x;
    const int t    = threadIdx.x;
    const int half = t >> 7;         // 0 = A (even spectrum), 1 = B (odd)
    const int th   = t & 127;
    const int hq   = half << 12;     // complex-element offset: 0 or 4096

    unsigned long long NEG1;
    asm("mov.b64 %0, 0xBF800000BF800000;" : "=l"(NEG1));

    const int REV4[16] = {0,8,4,12,2,10,6,14,1,9,5,13,3,11,7,15};

    // ---- Phase 0: coalesced stage of x into smem (swizzled floats) -------
    {
        const float4* x4 = (const float4*)(x + (size_t)row * NFFT);
        #pragma unroll
        for (int j = 0; j < 16; j++) {
            int idx = t + THREADS * j;
            float4 v = x4[idx];
            *(float4*)(smem + sxz(idx << 2)) = v;
        }
    }
    __syncthreads();

    cplx r[2][16];

    // ---- Phase 1a: build spectrum q_m (m = 2u for A, 2u+1 for B) ---------
    // s_m = conj(expk_m) * (x_m - j x_{N-m});  s_0 = 2 x_0
    // q_m = 0.5 * [ (s_m + s_{m+H}) + j*tau_m*(s_m - s_{m+H}) ],  tau = e1^4
    // e1 = e^{+j*pi*m/32768}; m steps by 512 across n1 -> rotate by pi/64.
    {
        const float cD = 0.99879545620517239271f;   // cos(pi/64)
        const float sD = 0.04906767432741801426f;   // sin(pi/64)
        #pragma unroll
        for (int j = 0; j < 2; j++) {
            const int tp = th + 128 * j;            // t' in [0,256)
            const int m0 = 2 * tp + half;
            float cb, sb;
            __sincosf((float)m0 * (PI_F / 32768.0f), &sb, &cb);
            #pragma unroll
            for (int n1 = 0; n1 < 16; n1++) {
                int m = 512 * n1 + m0;              // [0, 8192)
                float e2x = (cb - sb) * SQRT_HALF;  // e2 = e1 * e^{j*pi/4}
                float e2y = (cb + sb) * SQRT_HALF;
                float t2x = 2.0f * e2x * e2y;       // = cb^2 - sb^2
                float t2y = 2.0f * cb * sb;
                float tx  = t2x*t2x - t2y*t2y, ty = 2.0f*t2x*t2y;   // tau = e1^4

                float xm  = smem[sxz(m)];
                float xmH = smem[sxz(m + HN)];
                float xHm = smem[sxz(HN - m)];
                cplx s1, s2;
                if (m == 0) {
                    s1.x = 2.0f * xm; s1.y = 0.0f;
                } else {
                    float xNm = smem[sxz(NFFT - m)];
                    s1.x = xm * cb + xNm * sb;
                    s1.y = xm * sb - xNm * cb;
                }
                s2.x = xmH * e2x + xHm * e2y;
                s2.y = xmH * e2y - xHm * e2x;
                cplx u = padd(s1, s2);
                cplx v = psub(s1, s2, NEG1);
                r[j][n1].x = 0.5f * (u.x - (tx * v.y + ty * v.x));
                r[j][n1].y = 0.5f * (u.y + (tx * v.x - ty * v.y));

                float ncb = cb * cD - sb * sD;      // e1 *= e^{j*pi/64}
                sb = sb * cD + cb * sD;
                cb = ncb;
            }
        }
    }
    __syncthreads();   // all x reads done before overwriting smem

    // ---- Pass 1: radix-16 over n1, twiddle W_4096^{+t'*k1} ---------------
    #pragma unroll
    for (int j = 0; j < 2; j++) {
        fft16_inv(r[j], NEG1);
        const int tp = th + 128 * j;
        float w1s, w1c;
        __sincosf((float)tp * (2.0f * PI_F / 4096.0f), &w1s, &w1c);
        float wc = 1.0f, ws = 0.0f;                 // w^0
        #pragma unroll
        for (int k1 = 0; k1 < 16; k1++) {
            const int i = REV4[k1];                 // literal under unroll
            float vx = r[j][i].x * wc - r[j][i].y * ws;
            float vy = r[j][i].x * ws + r[j][i].y * wc;
            // swc(k1*256+tp) = k1*256 + (tp ^ k1) since tp < 256
            cz[hq + k1 * 256 + (tp ^ k1)] = make_float2(vx, vy);
            float nwc = wc * w1c - ws * w1s;        // w *= w1
            ws = ws * w1c + wc * w1s;
            wc = nwc;
        }
    }
    __syncthreads();

    // ---- Pass 2: radix-16 over middle digit, twiddle W_256^{+b*k2} -------
    // j=0 touches b in [0,8), j=1 touches b in [8,16): disjoint, no barrier.
    #pragma unroll
    for (int j = 0; j < 2; j++) {
        const int k1 = th & 15;
        const int b  = (th >> 4) + 8 * j;
        float2* base = cz + (hq + ((k1 * 256 + b) ^ k1));   // a*16 stays imm
        #pragma unroll
        for (int a = 0; a < 16; a++) {
            float2 v = base[a * 16];
            r[j][a].x = v.x; r[j][a].y = v.y;
        }
        fft16_inv(r[j], NEG1);
        float w1s, w1c;
        __sincosf((float)b * (PI_F / 128.0f), &w1s, &w1c);
        float wc = 1.0f, ws = 0.0f;
        #pragma unroll
        for (int k2 = 0; k2 < 16; k2++) {
            const int i = REV4[k2];
            float vx = r[j][i].x * wc - r[j][i].y * ws;
            float vy = r[j][i].x * ws + r[j][i].y * wc;
            base[k2 * 16] = make_float2(vx, vy);
            float nwc = wc * w1c - ws * w1s;
            ws = ws * w1c + wc * w1s;
            wc = nwc;
        }
    }
    __syncthreads();

    // ---- Pass 3: radix-16 over low digit, no twiddle ---------------------
    #pragma unroll
    for (int j = 0; j < 2; j++) {
        const int k1 = th & 15;
        const int c  = (th >> 4) + 8 * j;
        // element p = k1*256 + c*16 + d; swc: low4 = d ^ k1
        float2* base = cz + (hq + ((k1 * 256 + c * 16) ^ k1));
        #pragma unroll
        for (int bq = 0; bq < 16; bq++) {
            // careful: low-4 digit is bq here -> address = (k1*256 + c*16 + bq)^k1
            float2 v = cz[hq + ((k1 * 256 + c * 16 + bq) ^ k1)];
            r[j][bq].x = v.x; r[j][bq].y = v.y;
        }
        (void)base;
        fft16_inv(r[j], NEG1);
        #pragma unroll
        for (int i = 0; i < 16; i++) {
            int k3 = REV4[i];
            cz[hq + ((k1 * 256 + c * 16 + k3) ^ k1)] = make_float2(r[j][i].x, r[j][i].y);
        }
    }
    __syncthreads();

    // ---- Gather: combine halves + de-permute, contiguous float4 stores ---
    // z_q        = A_q        + w^q * B_q,        w = e^{+j*2*pi/8192}
    // z_{8191-q} = A_{4095-q} - w^{4095-q}*B_{4095-q},  -w^{4095-q} = conj(w^{q+1})*(-1)... folded below
    // y[4q]=Re z_q, y[4q+1]=Im z_{8191-q}, y[4q+2]=Im z_q, y[4q+3]=Re z_{8191-q}
    {
        float4* y4 = (float4*)(y + (size_t)row * NFFT);
        const float c1 = 0.99999970586288222663f;      // cos(2*pi/8192)
        const float s1 = 7.66990318742704526939e-4f;   // sin(2*pi/8192)
        const float cS = 0.98078528040323044913f;      // cos(pi/16)  (step: q += 256)
        const float sS = 0.19509032201612826785f;      // sin(pi/16)
        float wc, ws;
        __sincosf((float)t * (2.0f * PI_F / 8192.0f), &ws, &wc);
        const int d0 = t & 15, d1 = (t >> 4) & 15;     // q = t + 256j: low 8 bits fixed
        const int baseA = d0 * 256 + d1 * 16;          // + (j ^ d0) in low4 after swizzle
        const int baseM = (15 - d0) * 256 + (15 - d1) * 16;
        #pragma unroll
        for (int j = 0; j < 16; j++) {
            int q  = t + THREADS * j;                  // [0, 4096)
            int pA = baseA + (j ^ d0);
            int pM = baseM + ((15 - j) ^ (15 - d0));
            float2 A = cz[pA];
            float2 B = cz[pA + QN];
            float2 M = cz[pM];
            float2 Nw = cz[pM + QN];
            float ox = wc * c1 - ws * s1;              // w^{q+1}
            float oy = wc * s1 + ws * c1;
            cplx wB, oN, Ac, Mc;
            wB.x = wc * B.x - ws * B.y;
            wB.y = wc * B.y + ws * B.x;
            oN.x = ox * Nw.x + oy * Nw.y;
            oN.y = ox * Nw.y - oy * Nw.x;
            Ac.x = A.x; Ac.y = A.y;
            Mc.x = M.x; Mc.y = M.y;
            cplx z1 = padd(Ac, wB);
            cplx z2 = padd(Mc, oN);
            y4[q] = make_float4(z1.x, z2.y, z1.y, z2.x);
            float nwc = wc * cS - ws * sS;             // w *= e^{j*pi/16}
            ws = ws * cS + wc * sS;
            wc = nwc;
        }
    }
}

extern "C" void kernel_launch(void* const* d_in, const int* in_sizes, int n_in,
                              void* d_out, int out_size)
{
    const float* x = (const float*)d_in[0];
    float*       y = (float*)d_out;

    const int rows = in_sizes[0] / NFFT;
    const int smem_bytes = NFFT * (int)sizeof(float);   // 64 KB

    cudaFuncSetAttribute(idxct_kernel,
                         cudaFuncAttributeMaxDynamicSharedMemorySize, smem_bytes);

    idxct_kernel<<<rows, THREADS, smem_bytes>>>(x, y);
}

// round 9
// speedup vs baseline: 2.0281x; 1.0309x over previous
#include <cuda_runtime.h>

#define NFFT 16384
#define THREADS 256
#define PI_F 3.14159265358979323846f
#define SQRT_HALF 0.70710678118654752440f

// Inverse-FFT radix-16 twiddles: W_16^j = e^{+j*2*pi*j/16}, j=0..7
__constant__ float C16[8] = {
    1.0f, 0.92387953251128675613f, 0.70710678118654752440f, 0.38268343236508977173f,
    0.0f,-0.38268343236508977173f,-0.70710678118654752440f,-0.92387953251128675613f };
__constant__ float S16[8] = {
    0.0f, 0.38268343236508977173f, 0.70710678118654752440f, 0.92387953251128675613f,
    1.0f, 0.92387953251128675613f, 0.70710678118654752440f, 0.38268343236508977173f };

struct cplx { float x, y; };

__device__ __forceinline__ cplx padd(cplx a, cplx b) {
    cplx r;
    asm("{\n\t.reg .b64 ra, rb, rr;\n\t"
        "mov.b64 ra, {%2, %3};\n\tmov.b64 rb, {%4, %5};\n\t"
        "add.rn.f32x2 rr, ra, rb;\n\tmov.b64 {%0, %1}, rr;\n\t}"
        : "=f"(r.x), "=f"(r.y) : "f"(a.x), "f"(a.y), "f"(b.x), "f"(b.y));
    return r;
}
__device__ __forceinline__ cplx psub(cplx a, cplx b, unsigned long long neg1) {
    cplx r;
    asm("{\n\t.reg .b64 ra, rb, rr;\n\t"
        "mov.b64 ra, {%2, %3};\n\tmov.b64 rb, {%4, %5};\n\t"
        "fma.rn.f32x2 rr, rb, %6, ra;\n\tmov.b64 {%0, %1}, rr;\n\t}"
        : "=f"(r.x), "=f"(r.y) : "f"(a.x), "f"(a.y), "f"(b.x), "f"(b.y), "l"(neg1));
    return r;
}

// In-place DIF radix-16 inverse FFT (e^{+j}). Natural in, digit-reversed out.
__device__ __forceinline__ void fft16_inv(cplx* r, unsigned long long neg1) {
    #pragma unroll
    for (int half = 8; half >= 1; half >>= 1) {
        #pragma unroll
        for (int base = 0; base < 16; base += 2 * half) {
            #pragma unroll
            for (int j = 0; j < half; j++) {
                cplx a = r[base + j];
                cplx b = r[base + half + j];
                r[base + j] = padd(a, b);
                cplx d = psub(a, b, neg1);
                const int tw = j * (8 / half);
                if (tw == 0)      { r[base+half+j] = d; }
                else if (tw == 4) { r[base+half+j].x = -d.y; r[base+half+j].y = d.x; }
                else {
                    float c = C16[tw], s = S16[tw];
                    r[base+half+j].x = d.x * c - d.y * s;
                    r[base+half+j].y = d.x * s + d.y * c;
                }
            }
        }
    }
}

// Slot layout: F[4096] float4 slots; logical position pi -> slot pi ^ ((pi>>8)&15).
// Each slot holds two float2 halves (A,B); A at f2[2*sl + ha], B at f2[2*sl + 1-ha],
// where ha = bit3 of the slot's low digit (de-conflicts 16-lane LDS.64 phases).
__device__ __forceinline__ int slotof(int pi) { return pi ^ ((pi >> 8) & 15); }

__global__ void __launch_bounds__(THREADS, 3)
idxct_kernel(const float* __restrict__ x, float* __restrict__ y)
{
    extern __shared__ float smem[];
    float2* f2  = (float2*)smem;
    float4* f4p = (float4*)smem;

    const int row = blockIdx.x;
    const int t   = threadIdx.x;

    unsigned long long NEG1;
    asm("mov.b64 %0, 0xBF800000BF800000;" : "=l"(NEG1));

    const int REV4[16] = {0,8,4,12,2,10,6,14,1,9,5,13,3,11,7,15};

    // ---- Phase 0: stage x as pairs. Slot v holds (x[2v],x[2v+8192] | x[2v+1],x[2v+8193]).
    {
        const float4* x4 = (const float4*)(x + (size_t)row * NFFT);
        #pragma unroll
        for (int j = 0; j < 16; j++) {
            int v = t + THREADS * j;
            float4 a = x4[v >> 1];              // lane pairs dedup in coalescer
            float4 b = x4[(v >> 1) + 2048];
            int rs = v & 1;
            float xl0 = rs ? a.z : a.x, xl1 = rs ? a.w : a.y;
            float xh0 = rs ? b.z : b.x, xh1 = rs ? b.w : b.y;
            int sl = slotof(v);
            int ha = (sl >> 3) & 1;
            f4p[sl] = ha ? make_float4(xl1, xh1, xl0, xh0)
                         : make_float4(xl0, xh0, xl1, xh1);
        }
    }
    __syncthreads();

    // ---- Phase 1a: spectrum q_m in-place over pair slots.
    // Task (u, partner): m = 2u (A) or 2u+1 (B), partner m' = 8192-m.
    // s1'=conj(s2), s2'=conj(s1), tau'=-conj(tau)  =>  q' = 0.5*conj(u - g): 2 extra flops.
    {
        const float cD = 0.99879545620517239271f;   // cos(pi/64)
        const float sD = 0.04906767432741801426f;   // sin(pi/64)

        // A tasks: u = n1*256 + t (n1=0..7), m = 2u even, partner u'=4096-u.
        float cb, sb;
        __sincosf((float)(2 * t) * (PI_F / 32768.0f), &sb, &cb);
        #pragma unroll
        for (int n1 = 0; n1 < 8; n1++) {
            int u = n1 * 256 + t;
            if (u == 0) {
                // q_0 from pair[0]=(x0,x8192): s1=(2x0,0), s2=(sqrt2*x8192,0), tau=(1,0)
                float2 P = f2[0];                      // slot 0, ha=0 -> A at offset 0
                float ux = 2.0f * P.x + 2.0f * SQRT_HALF * P.y;
                float vx = 2.0f * P.x - 2.0f * SQRT_HALF * P.y;
                f2[0] = make_float2(0.5f * ux, 0.5f * vx);
                // q_2048 (m=4096, self-partner): pair[4096]=(x4096,x12288)
                {
                    const float c8 = 0.92387953251128675613f;  // cos(pi/8)
                    const float s8 = 0.38268343236508977173f;  // sin(pi/8)
                    int sl2 = slotof(2048);
                    int ha2 = (sl2 >> 3) & 1;
                    float2 P2 = f2[2 * sl2 + ha2];
                    float e2x = (c8 - s8) * SQRT_HALF, e2y = (c8 + s8) * SQRT_HALF;
                    float t2x = 2.0f * e2x * e2y, t2y = 2.0f * c8 * s8;
                    float tx = t2x * t2x - t2y * t2y, ty = 2.0f * t2x * t2y;
                    float s1x = P2.x * c8 + P2.y * s8, s1y = P2.x * s8 - P2.y * c8;
                    float s2x = P2.y * e2x + P2.x * e2y, s2y = P2.y * e2y - P2.x * e2x;
                    float ux2 = s1x + s2x, uy2 = s1y + s2y;
                    float vx2 = s1x - s2x, vy2 = s1y - s2y;
                    float gx = tx * vy2 + ty * vx2, gy = tx * vx2 - ty * vy2;
                    f2[2 * sl2 + ha2] = make_float2(0.5f * (ux2 - gx), 0.5f * (uy2 + gy));
                }
            } else {
                int up = 4096 - u;
                int slu = slotof(u),  hau = (slu >> 3) & 1;
                int slp = slotof(up), hap = (slp >> 3) & 1;
                float2 P = f2[2 * slu + hau];   // (x_m, x_{m+8192})
                float2 Q = f2[2 * slp + hap];   // (x_{8192-m}, x_{16384-m})
                float e2x = (cb - sb) * SQRT_HALF, e2y = (cb + sb) * SQRT_HALF;
                float t2x = 2.0f * e2x * e2y, t2y = 2.0f * cb * sb;
                float tx = t2x * t2x - t2y * t2y, ty = 2.0f * t2x * t2y;
                float s1x = P.x * cb + Q.y * sb,  s1y = P.x * sb - Q.y * cb;
                float s2x = P.y * e2x + Q.x * e2y, s2y = P.y * e2y - Q.x * e2x;
                float ux = s1x + s2x, uy = s1y + s2y;
                float vx = s1x - s2x, vy = s1y - s2y;
                float gx = tx * vy + ty * vx, gy = tx * vx - ty * vy;
                f2[2 * slu + hau] = make_float2(0.5f * (ux - gx), 0.5f * (uy + gy));
                f2[2 * slp + hap] = make_float2(0.5f * (ux + gx), 0.5f * (gy - uy));
            }
            float ncb = cb * cD - sb * sD;      // advance e1 by e^{j*pi/64}
            sb = sb * cD + cb * sD;
            cb = ncb;
        }

        // B tasks: u = n1*256 + t, m = 2u+1 odd, partner u'=4095-u. All proper pairs.
        __sincosf((float)(2 * t + 1) * (PI_F / 32768.0f), &sb, &cb);
        #pragma unroll
        for (int n1 = 0; n1 < 8; n1++) {
            int u = n1 * 256 + t;
            int up = 4095 - u;
            int slu = slotof(u),  hau = (slu >> 3) & 1;
            int slp = slotof(up), hap = (slp >> 3) & 1;
            float2 P = f2[2 * slu + (hau ^ 1)];   // B half: (x_m, x_{m+8192})
            float2 Q = f2[2 * slp + (hap ^ 1)];   // (x_{8192-m}, x_{16384-m})
            float e2x = (cb - sb) * SQRT_HALF, e2y = (cb + sb) * SQRT_HALF;
            float t2x = 2.0f * e2x * e2y, t2y = 2.0f * cb * sb;
            float tx = t2x * t2x - t2y * t2y, ty = 2.0f * t2x * t2y;
            float s1x = P.x * cb + Q.y * sb,  s1y = P.x * sb - Q.y * cb;
            float s2x = P.y * e2x + Q.x * e2y, s2y = P.y * e2y - Q.x * e2x;
            float ux = s1x + s2x, uy = s1y + s2y;
            float vx = s1x - s2x, vy = s1y - s2y;
            float gx = tx * vy + ty * vx, gy = tx * vx - ty * vy;
            f2[2 * slu + (hau ^ 1)] = make_float2(0.5f * (ux - gx), 0.5f * (uy + gy));
            f2[2 * slp + (hap ^ 1)] = make_float2(0.5f * (ux + gx), 0.5f * (gy - uy));
            float ncb = cb * cD - sb * sD;
            sb = sb * cD + cb * sD;
            cb = ncb;
        }
    }
    __syncthreads();

    // ---- Pass 1: radix-16 over n1, twiddle W_4096^{+t*k1}. In-place per thread.
    {
        float w1c, w1s;
        __sincosf((float)t * (2.0f * PI_F / 4096.0f), &w1s, &w1c);
        #pragma unroll
        for (int h = 0; h < 2; h++) {
            cplx r[16];
            #pragma unroll
            for (int n1 = 0; n1 < 16; n1++) {
                int sl = (n1 * 256 + t) ^ n1;
                int off = (((sl >> 3) & 1) ^ h);
                float2 v = f2[2 * sl + off];
                r[n1].x = v.x; r[n1].y = v.y;
            }
            fft16_inv(r, NEG1);
            float wc = 1.0f, ws = 0.0f;
            #pragma unroll
            for (int k1 = 0; k1 < 16; k1++) {
                const int i = REV4[k1];
                float vx = r[i].x * wc - r[i].y * ws;
                float vy = r[i].x * ws + r[i].y * wc;
                int sl = (k1 * 256 + t) ^ k1;
                int off = (((sl >> 3) & 1) ^ h);
                f2[2 * sl + off] = make_float2(vx, vy);
                float nwc = wc * w1c - ws * w1s;
                ws = ws * w1c + wc * w1s;
                wc = nwc;
            }
        }
    }
    __syncthreads();

    // ---- Pass 2: radix-16 over middle digit, twiddle W_256^{+b*k2}. In-place.
    {
        const int k1 = t & 15;
        const int b  = t >> 4;
        float w2c, w2s;
        __sincosf((float)b * (PI_F / 128.0f), &w2s, &w2c);
        const int slbase = (k1 << 8) + (b ^ k1);
        #pragma unroll
        for (int h = 0; h < 2; h++) {
            const int off = ((((b ^ k1) >> 3) & 1) ^ h);
            cplx r[16];
            #pragma unroll
            for (int a = 0; a < 16; a++) {
                float2 v = f2[2 * (slbase + a * 16) + off];
                r[a].x = v.x; r[a].y = v.y;
            }
            fft16_inv(r, NEG1);
            float wc = 1.0f, ws = 0.0f;
            #pragma unroll
            for (int k2 = 0; k2 < 16; k2++) {
                const int i = REV4[k2];
                float vx = r[i].x * wc - r[i].y * ws;
                float vy = r[i].x * ws + r[i].y * wc;
                f2[2 * (slbase + k2 * 16) + off] = make_float2(vx, vy);
                float nwc = wc * w2c - ws * w2s;
                ws = ws * w2c + wc * w2s;
                wc = nwc;
            }
        }
    }
    __syncthreads();

    // ---- Pass 3 + radix-2 combine: z_q = A + w^q B, z_{q+4096} = A - w^q B. In-place.
    {
        const int k1 = t & 15;
        const int c  = t >> 4;
        const int base0 = (k1 << 8) + (c << 4);
        cplx rA[16], rB[16];
        #pragma unroll
        for (int d = 0; d < 16; d++) {
            int lo = d ^ k1;
            float4 g = f4p[base0 + lo];
            if ((lo >> 3) & 1) { rA[d].x = g.z; rA[d].y = g.w; rB[d].x = g.x; rB[d].y = g.y; }
            else               { rA[d].x = g.x; rA[d].y = g.y; rB[d].x = g.z; rB[d].y = g.w; }
        }
        fft16_inv(rA, NEG1);
        fft16_inv(rB, NEG1);
        // w^q, q = k3*256 + c*16 + k1; step e^{j*pi/16}
        const float cS = 0.98078528040323044913f;   // cos(pi/16)
        const float sS = 0.19509032201612826785f;   // sin(pi/16)
        float wc, ws;
        __sincosf((float)(c * 16 + k1) * (2.0f * PI_F / 8192.0f), &ws, &wc);
        #pragma unroll
        for (int k3 = 0; k3 < 16; k3++) {
            const int i = REV4[k3];
            cplx wB;
            wB.x = rB[i].x * wc - rB[i].y * ws;
            wB.y = rB[i].x * ws + rB[i].y * wc;
            cplx zA = padd(rA[i], wB);
            cplx zB = psub(rA[i], wB, NEG1);
            int lo = k3 ^ k1;
            f4p[base0 + lo] = ((lo >> 3) & 1)
                ? make_float4(zB.x, zB.y, zA.x, zA.y)
                : make_float4(zA.x, zA.y, zB.x, zB.y);
            float nwc = wc * cS - ws * sS;
            ws = ws * cS + wc * sS;
            wc = nwc;
        }
    }
    __syncthreads();

    // ---- Gather: y4[qo] = (Re z_qo, Im z_{8191-qo}, Im z_qo, Re z_{8191-qo}).
    {
        float4* y4 = (float4*)(y + (size_t)row * NFFT);
        const int d0 = t & 15, d1 = (t >> 4) & 15;
        const int baseA = (d0 << 8) + (d1 << 4);
        const int baseM = ((15 - d0) << 8) + ((15 - d1) << 4);
        #pragma unroll
        for (int jj = 0; jj < 16; jj++) {
            int qo = t + THREADS * jj;
            int loA = jj ^ d0;
            float2 z1 = f2[2 * (baseA + loA) + (((loA >> 3) & 1))];          // A: z_qo
            int loM = (15 - jj) ^ (15 - d0);
            float2 z2 = f2[2 * (baseM + loM) + (((loM >> 3) & 1) ^ 1)];      // B: z_{8191-qo}
            y4[qo] = make_float4(z1.x, z2.y, z1.y, z2.x);
        }
    }
}

extern "C" void kernel_launch(void* const* d_in, const int* in_sizes, int n_in,
                              void* d_out, int out_size)
{
    const float* x = (const float*)d_in[0];
    float*       y = (float*)d_out;

    const int rows = in_sizes[0] / NFFT;
    const int smem_bytes = NFFT * (int)sizeof(float);   // 64 KB

    cudaFuncSetAttribute(idxct_kernel,
                         cudaFuncAttributeMaxDynamicSharedMemorySize, smem_bytes);

    idxct_kernel<<<rows, THREADS, smem_bytes>>>(x, y);
}